// round 2
// baseline (speedup 1.0000x reference)
#include <cuda_runtime.h>
#include <cuda_bf16.h>
#include <math.h>

#define N_NODES 20000
#define N_EDGES 200000
#define ET      220000    // edges + self loops
#define NFEAT   2048
#define H1      512
#define H2      30

// ------------------------- device scratch -------------------------
__device__ float g_xw1[(size_t)N_NODES * H1];
__device__ float g_h1 [(size_t)N_NODES * H1];
__device__ float g_xw3[(size_t)N_NODES * H1];
__device__ float g_h3 [(size_t)N_NODES * H1];
__device__ float g_h2 [(size_t)N_NODES * H2];
__device__ float g_a1s[N_NODES];
__device__ float g_a1d[N_NODES];
__device__ float g_den[N_NODES];
__device__ int   g_count[N_NODES];
__device__ int   g_cursor[N_NODES];
__device__ int   g_rowptr[N_NODES + 1];
__device__ int   g_srcs[ET];
__device__ float g_exs[ET];
__device__ double g_mse;

// ------------------------- init -------------------------
__global__ void init_kernel() {
    int i = blockIdx.x * blockDim.x + threadIdx.x;
    if (i < N_NODES) {
        g_den[i] = 0.f;
        g_count[i] = 0;
        g_cursor[i] = 0;
    }
    if (i == 0) g_mse = 0.0;
}

// ------------------------- SGEMM NN: C[M,N] = A[M,K] @ B[K,N] -------------------------
// BM=128 BN=128 BK=16, 256 threads, 8x8 microtile.
#define BM 128
#define BN 128
#define BK 16
#define TM 8
#define TN 8

__global__ __launch_bounds__(256) void sgemm_nn(const float* __restrict__ A,
                                                const float* __restrict__ B,
                                                float* __restrict__ C,
                                                int M, int NN, int K) {
    __shared__ float As[BK][BM + 4];
    __shared__ float Bs[BK][BN];
    int bm = blockIdx.x * BM, bn = blockIdx.y * BN;
    int tid = threadIdx.x;
    int tr = tid / 16, tc = tid % 16;

    float acc[TM][TN];
#pragma unroll
    for (int i = 0; i < TM; i++)
#pragma unroll
        for (int j = 0; j < TN; j++) acc[i][j] = 0.f;

    for (int k0 = 0; k0 < K; k0 += BK) {
        // A tile [BM x BK] -> transposed smem As[k][m]
#pragma unroll
        for (int it = 0; it < 2; ++it) {
            int p = tid + it * 256;            // 512 float4 loads
            int row = p >> 2, kq = (p & 3) * 4;
            int gr = bm + row;
            float4 v = make_float4(0.f, 0.f, 0.f, 0.f);
            if (gr < M) v = *(const float4*)(A + (size_t)gr * K + k0 + kq);
            As[kq + 0][row] = v.x; As[kq + 1][row] = v.y;
            As[kq + 2][row] = v.z; As[kq + 3][row] = v.w;
        }
        // B tile [BK x BN] direct
#pragma unroll
        for (int it = 0; it < 2; ++it) {
            int p = tid + it * 256;
            int row = p >> 5, c4 = (p & 31) * 4;
            float4 v = *(const float4*)(B + (size_t)(k0 + row) * NN + bn + c4);
            *(float4*)&Bs[row][c4] = v;
        }
        __syncthreads();
#pragma unroll
        for (int k = 0; k < BK; k++) {
            float a[TM], b[TN];
#pragma unroll
            for (int i = 0; i < TM; i++) a[i] = As[k][tr * TM + i];
#pragma unroll
            for (int j = 0; j < TN; j++) b[j] = Bs[k][tc * TN + j];
#pragma unroll
            for (int i = 0; i < TM; i++)
#pragma unroll
                for (int j = 0; j < TN; j++) acc[i][j] = fmaf(a[i], b[j], acc[i][j]);
        }
        __syncthreads();
    }
#pragma unroll
    for (int i = 0; i < TM; i++) {
        int gr = bm + tr * TM + i;
        if (gr < M) {
#pragma unroll
            for (int j = 0; j < TN; j++)
                C[(size_t)gr * NN + bn + tc * TN + j] = acc[i][j];
        }
    }
}

// ------------------------- SGEMM NT + fused MSE -------------------------
// D[M,N] = A[M,K] @ Bt[N,K]^T ; accumulate sum((F - D)^2) into g_mse.
__global__ __launch_bounds__(256) void sgemm_nt_mse(const float* __restrict__ A,
                                                    const float* __restrict__ Bt,
                                                    const float* __restrict__ Ffeat,
                                                    int M, int NN, int K) {
    __shared__ float As[BK][BM + 4];
    __shared__ float Bs[BK][BN + 4];
    __shared__ float red[256];
    int bm = blockIdx.x * BM, bn = blockIdx.y * BN;
    int tid = threadIdx.x;
    int tr = tid / 16, tc = tid % 16;

    float acc[TM][TN];
#pragma unroll
    for (int i = 0; i < TM; i++)
#pragma unroll
        for (int j = 0; j < TN; j++) acc[i][j] = 0.f;

    for (int k0 = 0; k0 < K; k0 += BK) {
#pragma unroll
        for (int it = 0; it < 2; ++it) {
            int p = tid + it * 256;
            int row = p >> 2, kq = (p & 3) * 4;
            int gr = bm + row;
            float4 v = make_float4(0.f, 0.f, 0.f, 0.f);
            if (gr < M) v = *(const float4*)(A + (size_t)gr * K + k0 + kq);
            As[kq + 0][row] = v.x; As[kq + 1][row] = v.y;
            As[kq + 2][row] = v.z; As[kq + 3][row] = v.w;
        }
#pragma unroll
        for (int it = 0; it < 2; ++it) {
            int p = tid + it * 256;
            int row = p >> 2, kq = (p & 3) * 4;   // row indexes N dim here
            float4 v = *(const float4*)(Bt + (size_t)(bn + row) * K + k0 + kq);
            Bs[kq + 0][row] = v.x; Bs[kq + 1][row] = v.y;
            Bs[kq + 2][row] = v.z; Bs[kq + 3][row] = v.w;
        }
        __syncthreads();
#pragma unroll
        for (int k = 0; k < BK; k++) {
            float a[TM], b[TN];
#pragma unroll
            for (int i = 0; i < TM; i++) a[i] = As[k][tr * TM + i];
#pragma unroll
            for (int j = 0; j < TN; j++) b[j] = Bs[k][tc * TN + j];
#pragma unroll
            for (int i = 0; i < TM; i++)
#pragma unroll
                for (int j = 0; j < TN; j++) acc[i][j] = fmaf(a[i], b[j], acc[i][j]);
        }
        __syncthreads();
    }
    // fused MSE partial
    float part = 0.f;
#pragma unroll
    for (int i = 0; i < TM; i++) {
        int gr = bm + tr * TM + i;
        if (gr < M) {
#pragma unroll
            for (int j = 0; j < TN; j++) {
                float f = Ffeat[(size_t)gr * NN + bn + tc * TN + j];
                float d = f - acc[i][j];
                part = fmaf(d, d, part);
            }
        }
    }
    red[tid] = part;
    __syncthreads();
    for (int off = 128; off > 0; off >>= 1) {
        if (tid < off) red[tid] += red[tid + off];
        __syncthreads();
    }
    if (tid == 0) atomicAdd(&g_mse, (double)red[0]);
}

// ------------------------- attention logits -------------------------
__global__ void att_kernel(const float* __restrict__ att_s, const float* __restrict__ att_d) {
    int gw = (blockIdx.x * blockDim.x + threadIdx.x) >> 5;
    int lane = threadIdx.x & 31;
    if (gw >= N_NODES) return;
    const float* row = g_xw1 + (size_t)gw * H1;
    float ss = 0.f, sd = 0.f;
    for (int k = lane; k < H1; k += 32) {
        float x = row[k];
        ss = fmaf(x, att_s[k], ss);
        sd = fmaf(x, att_d[k], sd);
    }
#pragma unroll
    for (int off = 16; off > 0; off >>= 1) {
        ss += __shfl_xor_sync(0xffffffffu, ss, off);
        sd += __shfl_xor_sync(0xffffffffu, sd, off);
    }
    if (lane == 0) { g_a1s[gw] = ss; g_a1d[gw] = sd; }
}

// ------------------------- CSR build -------------------------
__global__ void count_kernel(const int* __restrict__ ei) {
    int e = blockIdx.x * blockDim.x + threadIdx.x;
    if (e >= ET) return;
    int dst = (e < N_EDGES) ? ei[N_EDGES + e] : (e - N_EDGES);
    atomicAdd(&g_count[dst], 1);
}

__global__ void scan_kernel() {
    __shared__ int part[1024];
    int t = threadIdx.x;
    const int PER = 20;                 // 1024*20 = 20480 >= 20000
    int base = t * PER;
    int local[PER];
    int s = 0;
#pragma unroll
    for (int i = 0; i < PER; i++) {
        int idx = base + i;
        int c = (idx < N_NODES) ? g_count[idx] : 0;
        local[i] = s; s += c;
    }
    part[t] = s;
    __syncthreads();
    for (int off = 1; off < 1024; off <<= 1) {
        int v = (t >= off) ? part[t - off] : 0;
        __syncthreads();
        part[t] += v;
        __syncthreads();
    }
    int pre = (t > 0) ? part[t - 1] : 0;
#pragma unroll
    for (int i = 0; i < PER; i++) {
        int idx = base + i;
        if (idx < N_NODES) g_rowptr[idx] = pre + local[i];
    }
    if (t == 1023) g_rowptr[N_NODES] = part[1023];
}

__global__ void fill_kernel(const int* __restrict__ ei) {
    int e = blockIdx.x * blockDim.x + threadIdx.x;
    if (e >= ET) return;
    int src, dst;
    if (e < N_EDGES) { src = ei[e]; dst = ei[N_EDGES + e]; }
    else { src = e - N_EDGES; dst = e - N_EDGES; }
    float z = g_a1s[src] + g_a1d[dst];
    float sg = 1.f / (1.f + expf(-z));    // sigmoid in (0,1)
    float ex = expf(sg);                  // softmax numerator (max-shift skipped: shift-invariant)
    int pos = g_rowptr[dst] + atomicAdd(&g_cursor[dst], 1);
    g_srcs[pos] = src;
    g_exs[pos] = ex;
    atomicAdd(&g_den[dst], ex);
}

// ------------------------- per-dst gather + elu -------------------------
// one block (128 threads) per dst node; 512 channels as float4.
__global__ __launch_bounds__(128) void gather_kernel(const float* __restrict__ X,
                                                     float* __restrict__ Out) {
    int i = blockIdx.x;
    int t = threadIdx.x;
    int beg = g_rowptr[i], end = g_rowptr[i + 1];
    float4 acc = make_float4(0.f, 0.f, 0.f, 0.f);
    for (int j = beg; j < end; j++) {
        int s = g_srcs[j];
        float w = g_exs[j];
        float4 v = *(const float4*)(X + (size_t)s * H1 + t * 4);
        acc.x = fmaf(w, v.x, acc.x);
        acc.y = fmaf(w, v.y, acc.y);
        acc.z = fmaf(w, v.z, acc.z);
        acc.w = fmaf(w, v.w, acc.w);
    }
    float inv = 1.f / g_den[i];
    float4 o;
    float x;
    x = acc.x * inv; o.x = (x > 0.f) ? x : (expf(x) - 1.f);
    x = acc.y * inv; o.y = (x > 0.f) ? x : (expf(x) - 1.f);
    x = acc.z * inv; o.z = (x > 0.f) ? x : (expf(x) - 1.f);
    x = acc.w * inv; o.w = (x > 0.f) ? x : (expf(x) - 1.f);
    *(float4*)(Out + (size_t)i * H1 + t * 4) = o;
}

// ------------------------- h2 = normalize(h1 @ W2) -------------------------
// warp per row; lane c<30 computes a full K=512 dot.
__global__ __launch_bounds__(256) void h2_kernel(const float* __restrict__ W2) {
    __shared__ float hrow[8][H1];
    int w = threadIdx.x >> 5, lane = threadIdx.x & 31;
    int r = blockIdx.x * 8 + w;
    if (r >= N_NODES) return;
    const float* src = g_h1 + (size_t)r * H1;
    for (int k = lane; k < H1; k += 32) hrow[w][k] = src[k];
    __syncwarp();
    float val = 0.f;
    if (lane < H2) {
        for (int k = 0; k < H1; k++)
            val = fmaf(hrow[w][k], W2[k * H2 + lane], val);
    }
    float sq = val * val;
#pragma unroll
    for (int off = 16; off > 0; off >>= 1) sq += __shfl_xor_sync(0xffffffffu, sq, off);
    float norm = sqrtf(sq);
    float inv = 1.f / fmaxf(norm, 1e-12f);
    if (lane < H2) g_h2[(size_t)r * H2 + lane] = val * inv;
}

// ------------------------- xw3 = h2 @ W2^T -------------------------
__global__ void xw3_kernel(const float* __restrict__ W2) {
    int idx = blockIdx.x * blockDim.x + threadIdx.x;
    if (idx >= N_NODES * H1) return;
    int r = idx >> 9, c = idx & 511;
    const float* h2r = g_h2 + (size_t)r * H2;
    const float* w2r = W2 + (size_t)c * H2;
    float s = 0.f;
#pragma unroll
    for (int j = 0; j < H2; j++) s = fmaf(h2r[j], w2r[j], s);
    g_xw3[idx] = s;
}

// ------------------------- finalize -------------------------
__global__ void finalize_kernel(float* out) {
    out[0] = (float)(g_mse * (1.0 / ((double)N_NODES * (double)NFEAT)));
}

// ------------------------- launch -------------------------
extern "C" void kernel_launch(void* const* d_in, const int* in_sizes, int n_in,
                              void* d_out, int out_size) {
    const float* features = (const float*)d_in[0];
    const int*   ei       = (const int*)d_in[1];
    const float* W1       = (const float*)d_in[2];
    const float* att_src1 = (const float*)d_in[3];
    const float* att_dst1 = (const float*)d_in[4];
    const float* W2       = (const float*)d_in[5];
    float* out = (float*)d_out;

    // 0. init scratch
    init_kernel<<<(N_NODES + 255) / 256, 256>>>();

    // 1. xw1 = features @ W1   [20000,2048]x[2048,512]
    {
        dim3 grid((N_NODES + BM - 1) / BM, H1 / BN);
        sgemm_nn<<<grid, 256>>>(features, W1, g_xw1, N_NODES, H1, NFEAT);
    }

    // 2. attention logits
    att_kernel<<<(N_NODES * 32 + 255) / 256, 256>>>(att_src1, att_dst1);

    // 3. CSR build + edge softmax numerators/denominators
    count_kernel<<<(ET + 255) / 256, 256>>>(ei);
    scan_kernel<<<1, 1024>>>();
    fill_kernel<<<(ET + 255) / 256, 256>>>(ei);

    // 4. h1 = elu(propagate(xw1))
    gather_kernel<<<N_NODES, 128>>>(g_xw1, g_h1);

    // 5. h2 = normalize(h1 @ W2)
    h2_kernel<<<(N_NODES + 7) / 8, 256>>>(W2);

    // 6. xw3 = h2 @ W2^T
    xw3_kernel<<<(N_NODES * H1 + 255) / 256, 256>>>(W2);

    // 7. h3 = elu(propagate(xw3))  (same coefficients / CSR)
    gather_kernel<<<N_NODES, 128>>>(g_xw3, g_h3);

    // 8. fused h4 = h3 @ W1^T and MSE accumulation
    {
        dim3 grid((N_NODES + BM - 1) / BM, NFEAT / BN);
        sgemm_nt_mse<<<grid, 256>>>(g_h3, W1, features, N_NODES, NFEAT, H1);
    }

    // 9. write scalar
    finalize_kernel<<<1, 1>>>(out);
}

// round 3
// speedup vs baseline: 1.1634x; 1.1634x over previous
#include <cuda_runtime.h>
#include <cuda_bf16.h>
#include <math.h>

#define N_NODES 20000
#define N_EDGES 200000
#define ET      220000    // edges + self loops
#define NFEAT   2048
#define H1      512
#define H2      30

// ------------------------- device scratch -------------------------
__device__ float g_xw1[(size_t)N_NODES * H1];
__device__ float g_h1 [(size_t)N_NODES * H1];
__device__ float g_xw3[(size_t)N_NODES * H1];
__device__ float g_h3 [(size_t)N_NODES * H1];
__device__ float g_h2 [(size_t)N_NODES * H2];
__device__ float g_a1s[N_NODES];
__device__ float g_a1d[N_NODES];
__device__ float g_den[N_NODES];
__device__ int   g_count[N_NODES];
__device__ int   g_cursor[N_NODES];
__device__ int   g_rowptr[N_NODES + 1];
__device__ int   g_srcs[ET];
__device__ float g_exs[ET];
__device__ double g_mse;

// ------------------------- packed f32x2 helpers (sm_103a) -------------------------
__device__ __forceinline__ unsigned long long pk2(float lo, float hi) {
    unsigned long long r;
    asm("mov.b64 %0, {%1, %2};" : "=l"(r) : "f"(lo), "f"(hi));
    return r;
}
__device__ __forceinline__ void fma2(unsigned long long& d, unsigned long long a, unsigned long long b) {
    asm("fma.rn.f32x2 %0, %1, %2, %3;" : "=l"(d) : "l"(a), "l"(b), "l"(d));
}
__device__ __forceinline__ float2 upk2(unsigned long long v) {
    float2 f;
    asm("mov.b64 {%0, %1}, %2;" : "=f"(f.x), "=f"(f.y) : "l"(v));
    return f;
}

// ------------------------- init -------------------------
__global__ void init_kernel() {
    int i = blockIdx.x * blockDim.x + threadIdx.x;
    if (i < N_NODES) {
        g_den[i] = 0.f;
        g_count[i] = 0;
        g_cursor[i] = 0;
    }
    if (i == 0) g_mse = 0.0;
}

// ------------------------- SGEMM NN (f32x2): C[M,N] = A[M,K] @ B[K,N] ------------
// BM=128 BN=128 BK=16, 256 threads, 8x8 microtile as 8x4 packed pairs.
#define BM 128
#define BN 128
#define BK 16
#define TM 8
#define TN 8

__global__ __launch_bounds__(256, 2) void sgemm_nn(const float* __restrict__ A,
                                                   const float* __restrict__ B,
                                                   float* __restrict__ C,
                                                   int M, int NN, int K) {
    __shared__ float As[BK][BM + 4];
    __shared__ float Bs[BK][BN];
    int bm = blockIdx.x * BM, bn = blockIdx.y * BN;
    int tid = threadIdx.x;
    int tr = tid / 16, tc = tid % 16;

    unsigned long long acc[TM][TN / 2];
#pragma unroll
    for (int i = 0; i < TM; i++)
#pragma unroll
        for (int j = 0; j < TN / 2; j++) acc[i][j] = 0ull;

    // prefetch registers: 2 float4 for A, 2 float4 for B
    float4 pa[2], pb[2];
    // A: p = tid + it*256; row = p>>2 ; kq=(p&3)*4
    {
#pragma unroll
        for (int it = 0; it < 2; ++it) {
            int p = tid + it * 256;
            int row = p >> 2, kq = (p & 3) * 4;
            int gr = bm + row;
            pa[it] = make_float4(0.f, 0.f, 0.f, 0.f);
            if (gr < M) pa[it] = *(const float4*)(A + (size_t)gr * K + 0 + kq);
        }
#pragma unroll
        for (int it = 0; it < 2; ++it) {
            int p = tid + it * 256;
            int row = p >> 5, c4 = (p & 31) * 4;
            pb[it] = *(const float4*)(B + (size_t)(0 + row) * NN + bn + c4);
        }
    }

    for (int k0 = 0; k0 < K; k0 += BK) {
        // commit prefetched tile to smem
#pragma unroll
        for (int it = 0; it < 2; ++it) {
            int p = tid + it * 256;
            int row = p >> 2, kq = (p & 3) * 4;
            As[kq + 0][row] = pa[it].x; As[kq + 1][row] = pa[it].y;
            As[kq + 2][row] = pa[it].z; As[kq + 3][row] = pa[it].w;
        }
#pragma unroll
        for (int it = 0; it < 2; ++it) {
            int p = tid + it * 256;
            int row = p >> 5, c4 = (p & 31) * 4;
            *(float4*)&Bs[row][c4] = pb[it];
        }
        __syncthreads();

        // issue next tile's global loads (overlap with compute)
        int kn = k0 + BK;
        if (kn < K) {
#pragma unroll
            for (int it = 0; it < 2; ++it) {
                int p = tid + it * 256;
                int row = p >> 2, kq = (p & 3) * 4;
                int gr = bm + row;
                pa[it] = make_float4(0.f, 0.f, 0.f, 0.f);
                if (gr < M) pa[it] = *(const float4*)(A + (size_t)gr * K + kn + kq);
            }
#pragma unroll
            for (int it = 0; it < 2; ++it) {
                int p = tid + it * 256;
                int row = p >> 5, c4 = (p & 31) * 4;
                pb[it] = *(const float4*)(B + (size_t)(kn + row) * NN + bn + c4);
            }
        }

#pragma unroll
        for (int k = 0; k < BK; k++) {
            float4 a0 = *(const float4*)&As[k][tr * TM];
            float4 a1 = *(const float4*)&As[k][tr * TM + 4];
            float4 b0 = *(const float4*)&Bs[k][tc * TN];
            float4 b1 = *(const float4*)&Bs[k][tc * TN + 4];
            unsigned long long A2[8], B2[4];
            A2[0] = pk2(a0.x, a0.x); A2[1] = pk2(a0.y, a0.y);
            A2[2] = pk2(a0.z, a0.z); A2[3] = pk2(a0.w, a0.w);
            A2[4] = pk2(a1.x, a1.x); A2[5] = pk2(a1.y, a1.y);
            A2[6] = pk2(a1.z, a1.z); A2[7] = pk2(a1.w, a1.w);
            B2[0] = pk2(b0.x, b0.y); B2[1] = pk2(b0.z, b0.w);
            B2[2] = pk2(b1.x, b1.y); B2[3] = pk2(b1.z, b1.w);
#pragma unroll
            for (int i = 0; i < TM; i++)
#pragma unroll
                for (int j = 0; j < TN / 2; j++) fma2(acc[i][j], A2[i], B2[j]);
        }
        __syncthreads();
    }
#pragma unroll
    for (int i = 0; i < TM; i++) {
        int gr = bm + tr * TM + i;
        if (gr < M) {
            float2 c0 = upk2(acc[i][0]), c1 = upk2(acc[i][1]);
            float2 c2 = upk2(acc[i][2]), c3 = upk2(acc[i][3]);
            *(float4*)(C + (size_t)gr * NN + bn + tc * TN)     = make_float4(c0.x, c0.y, c1.x, c1.y);
            *(float4*)(C + (size_t)gr * NN + bn + tc * TN + 4) = make_float4(c2.x, c2.y, c3.x, c3.y);
        }
    }
}

// ------------------------- SGEMM NT (f32x2) + fused MSE -------------------------
// D[M,N] = A[M,K] @ Bt[N,K]^T ; accumulate sum((F - D)^2) into g_mse.
__global__ __launch_bounds__(256, 2) void sgemm_nt_mse(const float* __restrict__ A,
                                                       const float* __restrict__ Bt,
                                                       const float* __restrict__ Ffeat,
                                                       int M, int NN, int K) {
    __shared__ float As[BK][BM + 4];
    __shared__ float Bs[BK][BN + 4];
    __shared__ float red[256];
    int bm = blockIdx.x * BM, bn = blockIdx.y * BN;
    int tid = threadIdx.x;
    int tr = tid / 16, tc = tid % 16;

    unsigned long long acc[TM][TN / 2];
#pragma unroll
    for (int i = 0; i < TM; i++)
#pragma unroll
        for (int j = 0; j < TN / 2; j++) acc[i][j] = 0ull;

    float4 pa[2], pb[2];
#pragma unroll
    for (int it = 0; it < 2; ++it) {
        int p = tid + it * 256;
        int row = p >> 2, kq = (p & 3) * 4;
        int gr = bm + row;
        pa[it] = make_float4(0.f, 0.f, 0.f, 0.f);
        if (gr < M) pa[it] = *(const float4*)(A + (size_t)gr * K + kq);
        pb[it] = *(const float4*)(Bt + (size_t)(bn + row) * K + kq);
    }

    for (int k0 = 0; k0 < K; k0 += BK) {
#pragma unroll
        for (int it = 0; it < 2; ++it) {
            int p = tid + it * 256;
            int row = p >> 2, kq = (p & 3) * 4;
            As[kq + 0][row] = pa[it].x; As[kq + 1][row] = pa[it].y;
            As[kq + 2][row] = pa[it].z; As[kq + 3][row] = pa[it].w;
            Bs[kq + 0][row] = pb[it].x; Bs[kq + 1][row] = pb[it].y;
            Bs[kq + 2][row] = pb[it].z; Bs[kq + 3][row] = pb[it].w;
        }
        __syncthreads();

        int kn = k0 + BK;
        if (kn < K) {
#pragma unroll
            for (int it = 0; it < 2; ++it) {
                int p = tid + it * 256;
                int row = p >> 2, kq = (p & 3) * 4;
                int gr = bm + row;
                pa[it] = make_float4(0.f, 0.f, 0.f, 0.f);
                if (gr < M) pa[it] = *(const float4*)(A + (size_t)gr * K + kn + kq);
                pb[it] = *(const float4*)(Bt + (size_t)(bn + row) * K + kn + kq);
            }
        }

#pragma unroll
        for (int k = 0; k < BK; k++) {
            float4 a0 = *(const float4*)&As[k][tr * TM];
            float4 a1 = *(const float4*)&As[k][tr * TM + 4];
            float4 b0 = *(const float4*)&Bs[k][tc * TN];
            float4 b1 = *(const float4*)&Bs[k][tc * TN + 4];
            unsigned long long A2[8], B2[4];
            A2[0] = pk2(a0.x, a0.x); A2[1] = pk2(a0.y, a0.y);
            A2[2] = pk2(a0.z, a0.z); A2[3] = pk2(a0.w, a0.w);
            A2[4] = pk2(a1.x, a1.x); A2[5] = pk2(a1.y, a1.y);
            A2[6] = pk2(a1.z, a1.z); A2[7] = pk2(a1.w, a1.w);
            B2[0] = pk2(b0.x, b0.y); B2[1] = pk2(b0.z, b0.w);
            B2[2] = pk2(b1.x, b1.y); B2[3] = pk2(b1.z, b1.w);
#pragma unroll
            for (int i = 0; i < TM; i++)
#pragma unroll
                for (int j = 0; j < TN / 2; j++) fma2(acc[i][j], A2[i], B2[j]);
        }
        __syncthreads();
    }

    // fused MSE partial
    float part = 0.f;
#pragma unroll
    for (int i = 0; i < TM; i++) {
        int gr = bm + tr * TM + i;
        if (gr < M) {
            float4 f0 = *(const float4*)(Ffeat + (size_t)gr * NN + bn + tc * TN);
            float4 f1 = *(const float4*)(Ffeat + (size_t)gr * NN + bn + tc * TN + 4);
            float2 c0 = upk2(acc[i][0]), c1 = upk2(acc[i][1]);
            float2 c2 = upk2(acc[i][2]), c3 = upk2(acc[i][3]);
            float d;
            d = f0.x - c0.x; part = fmaf(d, d, part);
            d = f0.y - c0.y; part = fmaf(d, d, part);
            d = f0.z - c1.x; part = fmaf(d, d, part);
            d = f0.w - c1.y; part = fmaf(d, d, part);
            d = f1.x - c2.x; part = fmaf(d, d, part);
            d = f1.y - c2.y; part = fmaf(d, d, part);
            d = f1.z - c3.x; part = fmaf(d, d, part);
            d = f1.w - c3.y; part = fmaf(d, d, part);
        }
    }
    red[tid] = part;
    __syncthreads();
    for (int off = 128; off > 0; off >>= 1) {
        if (tid < off) red[tid] += red[tid + off];
        __syncthreads();
    }
    if (tid == 0) atomicAdd(&g_mse, (double)red[0]);
}

// ------------------------- attention logits -------------------------
__global__ void att_kernel(const float* __restrict__ att_s, const float* __restrict__ att_d) {
    int gw = (blockIdx.x * blockDim.x + threadIdx.x) >> 5;
    int lane = threadIdx.x & 31;
    if (gw >= N_NODES) return;
    const float* row = g_xw1 + (size_t)gw * H1;
    float ss = 0.f, sd = 0.f;
    for (int k = lane; k < H1; k += 32) {
        float x = row[k];
        ss = fmaf(x, att_s[k], ss);
        sd = fmaf(x, att_d[k], sd);
    }
#pragma unroll
    for (int off = 16; off > 0; off >>= 1) {
        ss += __shfl_xor_sync(0xffffffffu, ss, off);
        sd += __shfl_xor_sync(0xffffffffu, sd, off);
    }
    if (lane == 0) { g_a1s[gw] = ss; g_a1d[gw] = sd; }
}

// ------------------------- CSR build -------------------------
__global__ void count_kernel(const int* __restrict__ ei) {
    int e = blockIdx.x * blockDim.x + threadIdx.x;
    if (e >= ET) return;
    int dst = (e < N_EDGES) ? ei[N_EDGES + e] : (e - N_EDGES);
    atomicAdd(&g_count[dst], 1);
}

__global__ void scan_kernel() {
    __shared__ int part[1024];
    int t = threadIdx.x;
    const int PER = 20;                 // 1024*20 = 20480 >= 20000
    int base = t * PER;
    int local[PER];
    int s = 0;
#pragma unroll
    for (int i = 0; i < PER; i++) {
        int idx = base + i;
        int c = (idx < N_NODES) ? g_count[idx] : 0;
        local[i] = s; s += c;
    }
    part[t] = s;
    __syncthreads();
    for (int off = 1; off < 1024; off <<= 1) {
        int v = (t >= off) ? part[t - off] : 0;
        __syncthreads();
        part[t] += v;
        __syncthreads();
    }
    int pre = (t > 0) ? part[t - 1] : 0;
#pragma unroll
    for (int i = 0; i < PER; i++) {
        int idx = base + i;
        if (idx < N_NODES) g_rowptr[idx] = pre + local[i];
    }
    if (t == 1023) g_rowptr[N_NODES] = part[1023];
}

__global__ void fill_kernel(const int* __restrict__ ei) {
    int e = blockIdx.x * blockDim.x + threadIdx.x;
    if (e >= ET) return;
    int src, dst;
    if (e < N_EDGES) { src = ei[e]; dst = ei[N_EDGES + e]; }
    else { src = e - N_EDGES; dst = e - N_EDGES; }
    float z = g_a1s[src] + g_a1d[dst];
    float sg = 1.f / (1.f + expf(-z));    // sigmoid in (0,1)
    float ex = expf(sg);                  // softmax numerator (max-shift skipped: shift-invariant)
    int pos = g_rowptr[dst] + atomicAdd(&g_cursor[dst], 1);
    g_srcs[pos] = src;
    g_exs[pos] = ex;
    atomicAdd(&g_den[dst], ex);
}

// ------------------------- per-dst gather + elu -------------------------
__global__ __launch_bounds__(128) void gather_kernel(const float* __restrict__ X,
                                                     float* __restrict__ Out) {
    int i = blockIdx.x;
    int t = threadIdx.x;
    int beg = g_rowptr[i], end = g_rowptr[i + 1];
    float4 acc = make_float4(0.f, 0.f, 0.f, 0.f);
    for (int j = beg; j < end; j++) {
        int s = g_srcs[j];
        float w = g_exs[j];
        float4 v = *(const float4*)(X + (size_t)s * H1 + t * 4);
        acc.x = fmaf(w, v.x, acc.x);
        acc.y = fmaf(w, v.y, acc.y);
        acc.z = fmaf(w, v.z, acc.z);
        acc.w = fmaf(w, v.w, acc.w);
    }
    float inv = 1.f / g_den[i];
    float4 o;
    float x;
    x = acc.x * inv; o.x = (x > 0.f) ? x : (expf(x) - 1.f);
    x = acc.y * inv; o.y = (x > 0.f) ? x : (expf(x) - 1.f);
    x = acc.z * inv; o.z = (x > 0.f) ? x : (expf(x) - 1.f);
    x = acc.w * inv; o.w = (x > 0.f) ? x : (expf(x) - 1.f);
    *(float4*)(Out + (size_t)i * H1 + t * 4) = o;
}

// ------------------------- h2 = normalize(h1 @ W2) -------------------------
__global__ __launch_bounds__(256) void h2_kernel(const float* __restrict__ W2) {
    __shared__ float hrow[8][H1];
    int w = threadIdx.x >> 5, lane = threadIdx.x & 31;
    int r = blockIdx.x * 8 + w;
    if (r >= N_NODES) return;
    const float* src = g_h1 + (size_t)r * H1;
    for (int k = lane; k < H1; k += 32) hrow[w][k] = src[k];
    __syncwarp();
    float val = 0.f;
    if (lane < H2) {
        for (int k = 0; k < H1; k++)
            val = fmaf(hrow[w][k], W2[k * H2 + lane], val);
    }
    float sq = val * val;
#pragma unroll
    for (int off = 16; off > 0; off >>= 1) sq += __shfl_xor_sync(0xffffffffu, sq, off);
    float norm = sqrtf(sq);
    float inv = 1.f / fmaxf(norm, 1e-12f);
    if (lane < H2) g_h2[(size_t)r * H2 + lane] = val * inv;
}

// ------------------------- xw3 = h2 @ W2^T as a tiled GEMM -------------------------
// C[M=20000, N=512] = h2[M,30] @ B[30,512] where B[k][c] = W2[c*30+k].
// Smem-tiled: removes the 614M scattered LDGs of the naive version.
__global__ __launch_bounds__(256) void xw3_gemm(const float* __restrict__ W2) {
    __shared__ float As[H2][BM + 4];   // 30 x 132
    __shared__ float Bs[H2][BN + 4];   // 30 x 132
    int bm = blockIdx.x * BM, bn = blockIdx.y * BN;
    int tid = threadIdx.x;
    int tr = tid / 16, tc = tid % 16;

    // load A tile: h2 rows [bm..bm+127], 30 cols
    for (int idx = tid; idx < BM * H2; idx += 256) {
        int row = idx / H2, k = idx - row * H2;
        int gr = bm + row;
        As[k][row] = (gr < N_NODES) ? g_h2[(size_t)gr * H2 + k] : 0.f;
    }
    // load B tile: Bs[k][c] = W2[(bn+c)*30 + k]
    for (int idx = tid; idx < BN * H2; idx += 256) {
        int c = idx / H2, k = idx - c * H2;
        Bs[k][c] = W2[(size_t)(bn + c) * H2 + k];
    }
    __syncthreads();

    float acc[TM][TN];
#pragma unroll
    for (int i = 0; i < TM; i++)
#pragma unroll
        for (int j = 0; j < TN; j++) acc[i][j] = 0.f;

#pragma unroll
    for (int k = 0; k < H2; k++) {
        float a[TM], b[TN];
#pragma unroll
        for (int i = 0; i < TM; i++) a[i] = As[k][tr * TM + i];
#pragma unroll
        for (int j = 0; j < TN; j++) b[j] = Bs[k][tc * TN + j];
#pragma unroll
        for (int i = 0; i < TM; i++)
#pragma unroll
            for (int j = 0; j < TN; j++) acc[i][j] = fmaf(a[i], b[j], acc[i][j]);
    }

#pragma unroll
    for (int i = 0; i < TM; i++) {
        int gr = bm + tr * TM + i;
        if (gr < N_NODES) {
#pragma unroll
            for (int j = 0; j < TN; j += 4) {
                *(float4*)(g_xw3 + (size_t)gr * H1 + bn + tc * TN + j) =
                    make_float4(acc[i][j], acc[i][j + 1], acc[i][j + 2], acc[i][j + 3]);
            }
        }
    }
}

// ------------------------- finalize -------------------------
__global__ void finalize_kernel(float* out) {
    out[0] = (float)(g_mse * (1.0 / ((double)N_NODES * (double)NFEAT)));
}

// ------------------------- launch -------------------------
extern "C" void kernel_launch(void* const* d_in, const int* in_sizes, int n_in,
                              void* d_out, int out_size) {
    const float* features = (const float*)d_in[0];
    const int*   ei       = (const int*)d_in[1];
    const float* W1       = (const float*)d_in[2];
    const float* att_src1 = (const float*)d_in[3];
    const float* att_dst1 = (const float*)d_in[4];
    const float* W2       = (const float*)d_in[5];
    float* out = (float*)d_out;

    // 0. init scratch
    init_kernel<<<(N_NODES + 255) / 256, 256>>>();

    // 1. xw1 = features @ W1   [20000,2048]x[2048,512]
    {
        dim3 grid((N_NODES + BM - 1) / BM, H1 / BN);
        sgemm_nn<<<grid, 256>>>(features, W1, g_xw1, N_NODES, H1, NFEAT);
    }

    // 2. attention logits
    att_kernel<<<(N_NODES * 32 + 255) / 256, 256>>>(att_src1, att_dst1);

    // 3. CSR build + edge softmax numerators/denominators
    count_kernel<<<(ET + 255) / 256, 256>>>(ei);
    scan_kernel<<<1, 1024>>>();
    fill_kernel<<<(ET + 255) / 256, 256>>>(ei);

    // 4. h1 = elu(propagate(xw1))
    gather_kernel<<<N_NODES, 128>>>(g_xw1, g_h1);

    // 5. h2 = normalize(h1 @ W2)
    h2_kernel<<<(N_NODES + 7) / 8, 256>>>(W2);

    // 6. xw3 = h2 @ W2^T  (tiled GEMM)
    {
        dim3 grid((N_NODES + BM - 1) / BM, H1 / BN);
        xw3_gemm<<<grid, 256>>>(W2);
    }

    // 7. h3 = elu(propagate(xw3))  (same coefficients / CSR)
    gather_kernel<<<N_NODES, 128>>>(g_xw3, g_h3);

    // 8. fused h4 = h3 @ W1^T and MSE accumulation
    {
        dim3 grid((N_NODES + BM - 1) / BM, NFEAT / BN);
        sgemm_nt_mse<<<grid, 256>>>(g_h3, W1, features, N_NODES, NFEAT, H1);
    }

    // 9. write scalar
    finalize_kernel<<<1, 1>>>(out);
}

// round 5
// speedup vs baseline: 1.3900x; 1.1948x over previous
#include <cuda_runtime.h>
#include <cuda_bf16.h>
#include <math.h>
#include <stdint.h>

#define N_NODES 20000
#define N_EDGES 200000
#define ET      220000    // edges + self loops
#define NFEAT   2048
#define H1      512
#define H2      30

// ------------------------- device scratch -------------------------
__device__ float g_xw1[(size_t)N_NODES * H1];
__device__ float g_h1 [(size_t)N_NODES * H1];
__device__ float g_xw3[(size_t)N_NODES * H1];
__device__ float g_h3 [(size_t)N_NODES * H1];
__device__ float g_h2 [(size_t)N_NODES * H2];
__device__ float g_a1s[N_NODES];
__device__ float g_a1d[N_NODES];
__device__ float g_den[N_NODES];
__device__ int   g_count[N_NODES];
__device__ int   g_cursor[N_NODES];
__device__ int   g_rowptr[N_NODES + 1];
__device__ int   g_srcs[ET];
__device__ float g_exs[ET];
__device__ double g_mse;

// ------------------------- tf32 helpers -------------------------
__device__ __forceinline__ uint32_t f2tf(float x) {
    uint32_t r;
    asm("cvt.rna.tf32.f32 %0, %1;" : "=r"(r) : "f"(x));
    return r;
}
__device__ __forceinline__ void mma_tf32(float c[4], const uint32_t a[4], const uint32_t b[2]) {
    asm("mma.sync.aligned.m16n8k8.row.col.f32.tf32.tf32.f32 "
        "{%0,%1,%2,%3}, {%4,%5,%6,%7}, {%8,%9}, {%0,%1,%2,%3};"
        : "+f"(c[0]), "+f"(c[1]), "+f"(c[2]), "+f"(c[3])
        : "r"(a[0]), "r"(a[1]), "r"(a[2]), "r"(a[3]), "r"(b[0]), "r"(b[1]));
}

#define BM 128
#define BN 128
#define BK 32
#define SSTR 136                      // BM + 8 pad
#define SWZ(k, c) ((c) ^ ((((k) >> 2) & 3) << 3))

// ------------------------- init -------------------------
__global__ void init_kernel() {
    int i = blockIdx.x * blockDim.x + threadIdx.x;
    if (i < N_NODES) {
        g_den[i] = 0.f;
        g_count[i] = 0;
        g_cursor[i] = 0;
    }
    if (i == 0) g_mse = 0.0;
}

// ------------------------- TF32 GEMM NN: C[M,N] = A[M,K] @ B[K,N] -------------------------
__global__ __launch_bounds__(256, 1) void mm_nn_tf32(const float* __restrict__ A,
                                                     const float* __restrict__ B,
                                                     float* __restrict__ C,
                                                     int M, int NN, int K) {
    __shared__ uint32_t As[BK][SSTR];
    __shared__ uint32_t Bs[BK][SSTR];
    int bm = blockIdx.x * BM, bn = blockIdx.y * BN;
    int tid = threadIdx.x;
    int warp = tid >> 5, lane = tid & 31;
    int g = lane >> 2, tig = lane & 3;
    int wm = (warp & 1) * 64, wn = (warp >> 1) * 32;

    float acc[4][4][4];
#pragma unroll
    for (int mt = 0; mt < 4; mt++)
#pragma unroll
        for (int nt = 0; nt < 4; nt++)
#pragma unroll
            for (int q = 0; q < 4; q++) acc[mt][nt][q] = 0.f;

    float4 pa[4], pb[4];
    // prefetch tile k0=0
#pragma unroll
    for (int it = 0; it < 4; ++it) {
        int p = tid + it * 256;
        int arow = p >> 3, akq = (p & 7) * 4;
        int gr = bm + arow;
        pa[it] = make_float4(0.f, 0.f, 0.f, 0.f);
        if (gr < M) pa[it] = *(const float4*)(A + (size_t)gr * K + akq);
        int brow = p >> 5, bc4 = (p & 31) * 4;
        pb[it] = *(const float4*)(B + (size_t)brow * NN + bn + bc4);
    }

    for (int k0 = 0; k0 < K; k0 += BK) {
        // commit prefetched tile (cvt to tf32)
#pragma unroll
        for (int it = 0; it < 4; ++it) {
            int p = tid + it * 256;
            int arow = p >> 3, akq = (p & 7) * 4;
            As[akq + 0][SWZ(akq + 0, arow)] = f2tf(pa[it].x);
            As[akq + 1][SWZ(akq + 1, arow)] = f2tf(pa[it].y);
            As[akq + 2][SWZ(akq + 2, arow)] = f2tf(pa[it].z);
            As[akq + 3][SWZ(akq + 3, arow)] = f2tf(pa[it].w);
            int brow = p >> 5, bc4 = (p & 31) * 4;
            int col = SWZ(brow, bc4);
            uint4 v;
            v.x = f2tf(pb[it].x); v.y = f2tf(pb[it].y);
            v.z = f2tf(pb[it].z); v.w = f2tf(pb[it].w);
            *(uint4*)&Bs[brow][col] = v;
        }
        __syncthreads();

        int kn = k0 + BK;
        if (kn < K) {
#pragma unroll
            for (int it = 0; it < 4; ++it) {
                int p = tid + it * 256;
                int arow = p >> 3, akq = (p & 7) * 4;
                int gr = bm + arow;
                pa[it] = make_float4(0.f, 0.f, 0.f, 0.f);
                if (gr < M) pa[it] = *(const float4*)(A + (size_t)gr * K + kn + akq);
                int brow = p >> 5, bc4 = (p & 31) * 4;
                pb[it] = *(const float4*)(B + (size_t)(kn + brow) * NN + bn + bc4);
            }
        }

#pragma unroll
        for (int ka = 0; ka < 4; ka++) {
            int kb = ka * 8;
            uint32_t a[4][4], b[4][2];
#pragma unroll
            for (int mt = 0; mt < 4; mt++) {
                int m0 = wm + mt * 16;
                a[mt][0] = As[kb + tig][SWZ(kb + tig, m0 + g)];
                a[mt][1] = As[kb + tig][SWZ(kb + tig, m0 + g + 8)];
                a[mt][2] = As[kb + tig + 4][SWZ(kb + tig + 4, m0 + g)];
                a[mt][3] = As[kb + tig + 4][SWZ(kb + tig + 4, m0 + g + 8)];
            }
#pragma unroll
            for (int nt = 0; nt < 4; nt++) {
                int n0 = wn + nt * 8;
                b[nt][0] = Bs[kb + tig][SWZ(kb + tig, n0 + g)];
                b[nt][1] = Bs[kb + tig + 4][SWZ(kb + tig + 4, n0 + g)];
            }
#pragma unroll
            for (int mt = 0; mt < 4; mt++)
#pragma unroll
                for (int nt = 0; nt < 4; nt++)
                    mma_tf32(acc[mt][nt], a[mt], b[nt]);
        }
        __syncthreads();
    }

    // epilogue
#pragma unroll
    for (int mt = 0; mt < 4; mt++) {
        int r0 = bm + wm + mt * 16 + g;
        int r1 = r0 + 8;
#pragma unroll
        for (int nt = 0; nt < 4; nt++) {
            int c = bn + wn + nt * 8 + 2 * tig;
            if (r0 < M) *(float2*)(C + (size_t)r0 * NN + c) = make_float2(acc[mt][nt][0], acc[mt][nt][1]);
            if (r1 < M) *(float2*)(C + (size_t)r1 * NN + c) = make_float2(acc[mt][nt][2], acc[mt][nt][3]);
        }
    }
}

// ------------------------- TF32 GEMM NT + fused MSE -------------------------
// D[M,N] = A[M,K] @ Bt[N,K]^T ; accumulate sum((F - D)^2) into g_mse.
__global__ __launch_bounds__(256, 1) void mm_nt_mse_tf32(const float* __restrict__ A,
                                                         const float* __restrict__ Bt,
                                                         const float* __restrict__ Ffeat,
                                                         int M, int NN, int K) {
    __shared__ uint32_t As[BK][SSTR];
    __shared__ uint32_t Bs[BK][SSTR];
    __shared__ float red[256];
    int bm = blockIdx.x * BM, bn = blockIdx.y * BN;
    int tid = threadIdx.x;
    int warp = tid >> 5, lane = tid & 31;
    int g = lane >> 2, tig = lane & 3;
    int wm = (warp & 1) * 64, wn = (warp >> 1) * 32;

    float acc[4][4][4];
#pragma unroll
    for (int mt = 0; mt < 4; mt++)
#pragma unroll
        for (int nt = 0; nt < 4; nt++)
#pragma unroll
            for (int q = 0; q < 4; q++) acc[mt][nt][q] = 0.f;

    float4 pa[4], pb[4];
#pragma unroll
    for (int it = 0; it < 4; ++it) {
        int p = tid + it * 256;
        int arow = p >> 3, akq = (p & 7) * 4;
        int gr = bm + arow;
        pa[it] = make_float4(0.f, 0.f, 0.f, 0.f);
        if (gr < M) pa[it] = *(const float4*)(A + (size_t)gr * K + akq);
        pb[it] = *(const float4*)(Bt + (size_t)(bn + arow) * K + akq);
    }

    for (int k0 = 0; k0 < K; k0 += BK) {
#pragma unroll
        for (int it = 0; it < 4; ++it) {
            int p = tid + it * 256;
            int arow = p >> 3, akq = (p & 7) * 4;
            As[akq + 0][SWZ(akq + 0, arow)] = f2tf(pa[it].x);
            As[akq + 1][SWZ(akq + 1, arow)] = f2tf(pa[it].y);
            As[akq + 2][SWZ(akq + 2, arow)] = f2tf(pa[it].z);
            As[akq + 3][SWZ(akq + 3, arow)] = f2tf(pa[it].w);
            Bs[akq + 0][SWZ(akq + 0, arow)] = f2tf(pb[it].x);
            Bs[akq + 1][SWZ(akq + 1, arow)] = f2tf(pb[it].y);
            Bs[akq + 2][SWZ(akq + 2, arow)] = f2tf(pb[it].z);
            Bs[akq + 3][SWZ(akq + 3, arow)] = f2tf(pb[it].w);
        }
        __syncthreads();

        int kn = k0 + BK;
        if (kn < K) {
#pragma unroll
            for (int it = 0; it < 4; ++it) {
                int p = tid + it * 256;
                int arow = p >> 3, akq = (p & 7) * 4;
                int gr = bm + arow;
                pa[it] = make_float4(0.f, 0.f, 0.f, 0.f);
                if (gr < M) pa[it] = *(const float4*)(A + (size_t)gr * K + kn + akq);
                pb[it] = *(const float4*)(Bt + (size_t)(bn + arow) * K + kn + akq);
            }
        }

#pragma unroll
        for (int ka = 0; ka < 4; ka++) {
            int kb = ka * 8;
            uint32_t a[4][4], b[4][2];
#pragma unroll
            for (int mt = 0; mt < 4; mt++) {
                int m0 = wm + mt * 16;
                a[mt][0] = As[kb + tig][SWZ(kb + tig, m0 + g)];
                a[mt][1] = As[kb + tig][SWZ(kb + tig, m0 + g + 8)];
                a[mt][2] = As[kb + tig + 4][SWZ(kb + tig + 4, m0 + g)];
                a[mt][3] = As[kb + tig + 4][SWZ(kb + tig + 4, m0 + g + 8)];
            }
#pragma unroll
            for (int nt = 0; nt < 4; nt++) {
                int n0 = wn + nt * 8;
                b[nt][0] = Bs[kb + tig][SWZ(kb + tig, n0 + g)];
                b[nt][1] = Bs[kb + tig + 4][SWZ(kb + tig + 4, n0 + g)];
            }
#pragma unroll
            for (int mt = 0; mt < 4; mt++)
#pragma unroll
                for (int nt = 0; nt < 4; nt++)
                    mma_tf32(acc[mt][nt], a[mt], b[nt]);
        }
        __syncthreads();
    }

    // fused MSE epilogue
    float part = 0.f;
#pragma unroll
    for (int mt = 0; mt < 4; mt++) {
        int r0 = bm + wm + mt * 16 + g;
        int r1 = r0 + 8;
#pragma unroll
        for (int nt = 0; nt < 4; nt++) {
            int c = bn + wn + nt * 8 + 2 * tig;
            if (r0 < M) {
                float2 f = *(const float2*)(Ffeat + (size_t)r0 * NN + c);
                float d0 = f.x - acc[mt][nt][0], d1 = f.y - acc[mt][nt][1];
                part = fmaf(d0, d0, part);
                part = fmaf(d1, d1, part);
            }
            if (r1 < M) {
                float2 f = *(const float2*)(Ffeat + (size_t)r1 * NN + c);
                float d0 = f.x - acc[mt][nt][2], d1 = f.y - acc[mt][nt][3];
                part = fmaf(d0, d0, part);
                part = fmaf(d1, d1, part);
            }
        }
    }
    red[tid] = part;
    __syncthreads();
    for (int off = 128; off > 0; off >>= 1) {
        if (tid < off) red[tid] += red[tid + off];
        __syncthreads();
    }
    if (tid == 0) atomicAdd(&g_mse, (double)red[0]);
}

// ------------------------- attention logits -------------------------
__global__ void att_kernel(const float* __restrict__ att_s, const float* __restrict__ att_d) {
    int gw = (blockIdx.x * blockDim.x + threadIdx.x) >> 5;
    int lane = threadIdx.x & 31;
    if (gw >= N_NODES) return;
    const float* row = g_xw1 + (size_t)gw * H1;
    float ss = 0.f, sd = 0.f;
    for (int k = lane; k < H1; k += 32) {
        float x = row[k];
        ss = fmaf(x, att_s[k], ss);
        sd = fmaf(x, att_d[k], sd);
    }
#pragma unroll
    for (int off = 16; off > 0; off >>= 1) {
        ss += __shfl_xor_sync(0xffffffffu, ss, off);
        sd += __shfl_xor_sync(0xffffffffu, sd, off);
    }
    if (lane == 0) { g_a1s[gw] = ss; g_a1d[gw] = sd; }
}

// ------------------------- CSR build -------------------------
__global__ void count_kernel(const int* __restrict__ ei) {
    int e = blockIdx.x * blockDim.x + threadIdx.x;
    if (e >= ET) return;
    int dst = (e < N_EDGES) ? ei[N_EDGES + e] : (e - N_EDGES);
    atomicAdd(&g_count[dst], 1);
}

__global__ void scan_kernel() {
    __shared__ int part[1024];
    int t = threadIdx.x;
    const int PER = 20;                 // 1024*20 = 20480 >= 20000
    int base = t * PER;
    int local[PER];
    int s = 0;
#pragma unroll
    for (int i = 0; i < PER; i++) {
        int idx = base + i;
        int c = (idx < N_NODES) ? g_count[idx] : 0;
        local[i] = s; s += c;
    }
    part[t] = s;
    __syncthreads();
    for (int off = 1; off < 1024; off <<= 1) {
        int v = (t >= off) ? part[t - off] : 0;
        __syncthreads();
        part[t] += v;
        __syncthreads();
    }
    int pre = (t > 0) ? part[t - 1] : 0;
#pragma unroll
    for (int i = 0; i < PER; i++) {
        int idx = base + i;
        if (idx < N_NODES) g_rowptr[idx] = pre + local[i];
    }
    if (t == 1023) g_rowptr[N_NODES] = part[1023];
}

__global__ void fill_kernel(const int* __restrict__ ei) {
    int e = blockIdx.x * blockDim.x + threadIdx.x;
    if (e >= ET) return;
    int src, dst;
    if (e < N_EDGES) { src = ei[e]; dst = ei[N_EDGES + e]; }
    else { src = e - N_EDGES; dst = e - N_EDGES; }
    float z = g_a1s[src] + g_a1d[dst];
    float sg = 1.f / (1.f + expf(-z));    // sigmoid in (0,1)
    float ex = expf(sg);                  // softmax numerator (max-shift skipped: shift-invariant)
    int pos = g_rowptr[dst] + atomicAdd(&g_cursor[dst], 1);
    g_srcs[pos] = src;
    g_exs[pos] = ex;
    atomicAdd(&g_den[dst], ex);
}

// ------------------------- per-dst gather + elu -------------------------
__global__ __launch_bounds__(128) void gather_kernel(const float* __restrict__ X,
                                                     float* __restrict__ Out) {
    int i = blockIdx.x;
    int t = threadIdx.x;
    int beg = g_rowptr[i], end = g_rowptr[i + 1];
    float4 acc = make_float4(0.f, 0.f, 0.f, 0.f);
    for (int j = beg; j < end; j++) {
        int s = g_srcs[j];
        float w = g_exs[j];
        float4 v = *(const float4*)(X + (size_t)s * H1 + t * 4);
        acc.x = fmaf(w, v.x, acc.x);
        acc.y = fmaf(w, v.y, acc.y);
        acc.z = fmaf(w, v.z, acc.z);
        acc.w = fmaf(w, v.w, acc.w);
    }
    float inv = 1.f / g_den[i];
    float4 o;
    float x;
    x = acc.x * inv; o.x = (x > 0.f) ? x : (expf(x) - 1.f);
    x = acc.y * inv; o.y = (x > 0.f) ? x : (expf(x) - 1.f);
    x = acc.z * inv; o.z = (x > 0.f) ? x : (expf(x) - 1.f);
    x = acc.w * inv; o.w = (x > 0.f) ? x : (expf(x) - 1.f);
    *(float4*)(Out + (size_t)i * H1 + t * 4) = o;
}

// ------------------------- h2 = normalize(h1 @ W2) -------------------------
__global__ __launch_bounds__(256) void h2_kernel(const float* __restrict__ W2) {
    __shared__ float hrow[8][H1];
    int w = threadIdx.x >> 5, lane = threadIdx.x & 31;
    int r = blockIdx.x * 8 + w;
    if (r >= N_NODES) return;
    const float* src = g_h1 + (size_t)r * H1;
    for (int k = lane; k < H1; k += 32) hrow[w][k] = src[k];
    __syncwarp();
    float val = 0.f;
    if (lane < H2) {
        for (int k = 0; k < H1; k++)
            val = fmaf(hrow[w][k], W2[k * H2 + lane], val);
    }
    float sq = val * val;
#pragma unroll
    for (int off = 16; off > 0; off >>= 1) sq += __shfl_xor_sync(0xffffffffu, sq, off);
    float norm = sqrtf(sq);
    float inv = 1.f / fmaxf(norm, 1e-12f);
    if (lane < H2) g_h2[(size_t)r * H2 + lane] = val * inv;
}

// ------------------------- xw3 = h2 @ W2^T as a tiled GEMM -------------------------
#define TM 8
#define TN 8
__global__ __launch_bounds__(256) void xw3_gemm(const float* __restrict__ W2) {
    __shared__ float As2[H2][BM + 4];   // 30 x 132
    __shared__ float Bs2[H2][BN + 4];   // 30 x 132
    int bm = blockIdx.x * BM, bn = blockIdx.y * BN;
    int tid = threadIdx.x;
    int tr = tid / 16, tc = tid % 16;

    for (int idx = tid; idx < BM * H2; idx += 256) {
        int row = idx / H2, k = idx - row * H2;
        int gr = bm + row;
        As2[k][row] = (gr < N_NODES) ? g_h2[(size_t)gr * H2 + k] : 0.f;
    }
    for (int idx = tid; idx < BN * H2; idx += 256) {
        int c = idx / H2, k = idx - c * H2;
        Bs2[k][c] = W2[(size_t)(bn + c) * H2 + k];
    }
    __syncthreads();

    float acc[TM][TN];
#pragma unroll
    for (int i = 0; i < TM; i++)
#pragma unroll
        for (int j = 0; j < TN; j++) acc[i][j] = 0.f;

#pragma unroll
    for (int k = 0; k < H2; k++) {
        float a[TM], b[TN];
#pragma unroll
        for (int i = 0; i < TM; i++) a[i] = As2[k][tr * TM + i];
#pragma unroll
        for (int j = 0; j < TN; j++) b[j] = Bs2[k][tc * TN + j];
#pragma unroll
        for (int i = 0; i < TM; i++)
#pragma unroll
            for (int j = 0; j < TN; j++) acc[i][j] = fmaf(a[i], b[j], acc[i][j]);
    }

#pragma unroll
    for (int i = 0; i < TM; i++) {
        int gr = bm + tr * TM + i;
        if (gr < N_NODES) {
#pragma unroll
            for (int j = 0; j < TN; j += 4) {
                *(float4*)(g_xw3 + (size_t)gr * H1 + bn + tc * TN + j) =
                    make_float4(acc[i][j], acc[i][j + 1], acc[i][j + 2], acc[i][j + 3]);
            }
        }
    }
}

// ------------------------- finalize -------------------------
__global__ void finalize_kernel(float* out) {
    out[0] = (float)(g_mse * (1.0 / ((double)N_NODES * (double)NFEAT)));
}

// ------------------------- launch -------------------------
extern "C" void kernel_launch(void* const* d_in, const int* in_sizes, int n_in,
                              void* d_out, int out_size) {
    const float* features = (const float*)d_in[0];
    const int*   ei       = (const int*)d_in[1];
    const float* W1       = (const float*)d_in[2];
    const float* att_src1 = (const float*)d_in[3];
    const float* att_dst1 = (const float*)d_in[4];
    const float* W2       = (const float*)d_in[5];
    float* out = (float*)d_out;

    // 0. init scratch
    init_kernel<<<(N_NODES + 255) / 256, 256>>>();

    // 1. xw1 = features @ W1   [20000,2048]x[2048,512]  (tf32 tensor cores)
    {
        dim3 grid((N_NODES + BM - 1) / BM, H1 / BN);
        mm_nn_tf32<<<grid, 256>>>(features, W1, g_xw1, N_NODES, H1, NFEAT);
    }

    // 2. attention logits
    att_kernel<<<(N_NODES * 32 + 255) / 256, 256>>>(att_src1, att_dst1);

    // 3. CSR build + edge softmax numerators/denominators
    count_kernel<<<(ET + 255) / 256, 256>>>(ei);
    scan_kernel<<<1, 1024>>>();
    fill_kernel<<<(ET + 255) / 256, 256>>>(ei);

    // 4. h1 = elu(propagate(xw1))
    gather_kernel<<<N_NODES, 128>>>(g_xw1, g_h1);

    // 5. h2 = normalize(h1 @ W2)
    h2_kernel<<<(N_NODES + 7) / 8, 256>>>(W2);

    // 6. xw3 = h2 @ W2^T  (tiled GEMM)
    {
        dim3 grid((N_NODES + BM - 1) / BM, H1 / BN);
        xw3_gemm<<<grid, 256>>>(W2);
    }

    // 7. h3 = elu(propagate(xw3))  (same coefficients / CSR)
    gather_kernel<<<N_NODES, 128>>>(g_xw3, g_h3);

    // 8. fused h4 = h3 @ W1^T and MSE accumulation (tf32 tensor cores)
    {
        dim3 grid((N_NODES + BM - 1) / BM, NFEAT / BN);
        mm_nt_mse_tf32<<<grid, 256>>>(g_h3, W1, features, N_NODES, NFEAT, H1);
    }

    // 9. write scalar
    finalize_kernel<<<1, 1>>>(out);
}